// round 2
// baseline (speedup 1.0000x reference)
#include <cuda_runtime.h>

// ---------------------------------------------------------------------------
// Graph_drug: 2-stack GraphSAGE (sum aggr) + global mean pool + concat
//   mol:    N=200000, E=1e6,  dims 78 -> 156 -> 312 -> 128
//   clique: N=120000, E=5e5,  dims 92 -> 184 -> 368 -> 128
//   G=4096 graphs, out [G, 256] fp32
// ---------------------------------------------------------------------------

#define GRAPHS 4096

// Scratch: max live tensor is 200000*312 = 62.4M floats.
#define SCRATCH_ELEMS 62500000
__device__ float g_bufA[SCRATCH_ELEMS];
__device__ float g_bufB[SCRATCH_ELEMS];
__device__ float g_agg [SCRATCH_ELEMS];
__device__ int   g_cnt [2 * GRAPHS];

// ---------------------------------------------------------------------------
__global__ void zero_f(float* __restrict__ p, size_t n) {
    size_t i = (size_t)blockIdx.x * blockDim.x + threadIdx.x;
    size_t stride = (size_t)gridDim.x * blockDim.x;
    for (; i < n; i += stride) p[i] = 0.0f;
}

__global__ void zero_i(int* __restrict__ p, int n) {
    int i = blockIdx.x * blockDim.x + threadIdx.x;
    if (i < n) p[i] = 0;
}

// ---------------------------------------------------------------------------
// Edge scatter: agg[dst] += x[src].  One warp per edge; lanes stride D/2
// float2 elements (all feature dims are even).
__global__ void scatter_add(const float* __restrict__ x,
                            const int* __restrict__ ei,
                            int E, int D2,          // D2 = D/2
                            float* __restrict__ agg) {
    int w = (blockIdx.x * blockDim.x + threadIdx.x) >> 5;
    int lane = threadIdx.x & 31;
    if (w >= E) return;
    int src = ei[w];
    int dst = ei[E + w];
    const float2* xs = (const float2*)(x + (size_t)src * (D2 * 2));
    float* ad = agg + (size_t)dst * (D2 * 2);
    for (int d = lane; d < D2; d += 32) {
        float2 v = xs[d];
        atomicAdd(ad + 2 * d,     v.x);
        atomicAdd(ad + 2 * d + 1, v.y);
    }
}

// ---------------------------------------------------------------------------
// Fused SAGE GEMM: out = relu(agg @ Wl^T + bl + x @ Wr^T)
//   agg, x : [N, Din]   Wl, Wr : [Dout, Din] row-major   bl : [Dout]
// Tiled 64x64x16, 256 threads, 4x4 register tile per thread.
__global__ void sage_gemm(const float* __restrict__ A0,   // agg
                          const float* __restrict__ A1,   // x (root path)
                          const float* __restrict__ W0,   // Wl
                          const float* __restrict__ W1,   // Wr
                          const float* __restrict__ bias, // bl
                          float* __restrict__ out,
                          int N, int Din, int Dout) {
    const int BM = 64, BN = 64, BK = 16;
    __shared__ float As[BK][BM];
    __shared__ float Ws[BK][BN];

    int tid = threadIdx.x;          // 0..255
    int tr = tid >> 4;              // 0..15
    int tc = tid & 15;              // 0..15
    int rowBase = blockIdx.y * BM;
    int colBase = blockIdx.x * BN;

    float acc[4][4];
    #pragma unroll
    for (int i = 0; i < 4; ++i)
        #pragma unroll
        for (int j = 0; j < 4; ++j) acc[i][j] = 0.0f;

    #pragma unroll
    for (int phase = 0; phase < 2; ++phase) {
        const float* A = phase ? A1 : A0;
        const float* W = phase ? W1 : W0;
        for (int k0 = 0; k0 < Din; k0 += BK) {
            #pragma unroll
            for (int l = 0; l < 4; ++l) {
                int idx = tid * 4 + l;
                int m = idx >> 4;        // 0..63
                int k = idx & 15;        // 0..15
                int row = rowBase + m;
                int kk = k0 + k;
                As[k][m] = (row < N && kk < Din) ? A[(size_t)row * Din + kk] : 0.0f;
            }
            #pragma unroll
            for (int l = 0; l < 4; ++l) {
                int idx = tid * 4 + l;
                int n = idx >> 4;
                int k = idx & 15;
                int col = colBase + n;
                int kk = k0 + k;
                Ws[k][n] = (col < Dout && kk < Din) ? W[(size_t)col * Din + kk] : 0.0f;
            }
            __syncthreads();
            #pragma unroll
            for (int k = 0; k < BK; ++k) {
                float a[4], b[4];
                #pragma unroll
                for (int i = 0; i < 4; ++i) a[i] = As[k][tr * 4 + i];
                #pragma unroll
                for (int j = 0; j < 4; ++j) b[j] = Ws[k][tc * 4 + j];
                #pragma unroll
                for (int i = 0; i < 4; ++i)
                    #pragma unroll
                    for (int j = 0; j < 4; ++j)
                        acc[i][j] += a[i] * b[j];
            }
            __syncthreads();
        }
    }

    #pragma unroll
    for (int i = 0; i < 4; ++i) {
        int row = rowBase + tr * 4 + i;
        if (row >= N) continue;
        #pragma unroll
        for (int j = 0; j < 4; ++j) {
            int col = colBase + tc * 4 + j;
            if (col >= Dout) continue;
            float v = acc[i][j] + bias[col];
            out[(size_t)row * Dout + col] = v > 0.0f ? v : 0.0f;
        }
    }
}

// ---------------------------------------------------------------------------
// Global mean pool, pass 1: sums + counts via atomics. h is [N, 128].
__global__ void pool_add(const float* __restrict__ h,
                         const int* __restrict__ batch,
                         int N, float* __restrict__ out, int colOff,
                         int* __restrict__ cnt) {
    int w = (blockIdx.x * blockDim.x + threadIdx.x) >> 5;
    int lane = threadIdx.x & 31;
    if (w >= N) return;
    int g = batch[w];
    const float* hs = h + (size_t)w * 128;
    float* o = out + (size_t)g * 256 + colOff;
    #pragma unroll
    for (int c = lane; c < 128; c += 32)
        atomicAdd(o + c, hs[c]);
    if (lane == 0) atomicAdd(cnt + g, 1);
}

// Pass 2: divide by counts.
__global__ void pool_div(float* __restrict__ out, const int* __restrict__ cnt) {
    int i = blockIdx.x * blockDim.x + threadIdx.x;
    if (i >= GRAPHS * 256) return;
    int g = i >> 8;
    int c = i & 255;
    int n = (c < 128) ? cnt[g] : cnt[GRAPHS + g];
    out[i] /= (float)(n > 0 ? n : 1);
}

// ---------------------------------------------------------------------------
static void run_stack(const float* x0, const int* ei, int E,
                      const int* batch, int N,
                      const float* const* Wp,   // wl1,bl1,wr1,wl2,bl2,wr2,wl3,bl3,wr3
                      int d0, int d1, int d2, int d3,
                      float* bufA, float* bufB, float* agg,
                      float* out, int colOff, int* cnt) {
    int sc_blocks = (int)(((long long)E * 32 + 255) / 256);

    // Layer 1
    zero_f<<<2048, 256>>>(agg, (size_t)N * d0);
    scatter_add<<<sc_blocks, 256>>>(x0, ei, E, d0 / 2, agg);
    sage_gemm<<<dim3((d1 + 63) / 64, (N + 63) / 64), 256>>>(
        agg, x0, Wp[0], Wp[2], Wp[1], bufA, N, d0, d1);

    // Layer 2
    zero_f<<<2048, 256>>>(agg, (size_t)N * d1);
    scatter_add<<<sc_blocks, 256>>>(bufA, ei, E, d1 / 2, agg);
    sage_gemm<<<dim3((d2 + 63) / 64, (N + 63) / 64), 256>>>(
        agg, bufA, Wp[3], Wp[5], Wp[4], bufB, N, d1, d2);

    // Layer 3
    zero_f<<<2048, 256>>>(agg, (size_t)N * d2);
    scatter_add<<<sc_blocks, 256>>>(bufB, ei, E, d2 / 2, agg);
    sage_gemm<<<dim3((d3 + 63) / 64, (N + 63) / 64), 256>>>(
        agg, bufB, Wp[6], Wp[8], Wp[7], bufA, N, d2, d3);

    // Pool (sums + counts)
    pool_add<<<(int)(((long long)N * 32 + 255) / 256), 256>>>(
        bufA, batch, N, out, colOff, cnt);
}

extern "C" void kernel_launch(void* const* d_in, const int* in_sizes, int n_in,
                              void* d_out, int out_size) {
    const float* x      = (const float*)d_in[0];
    const int*   ei     = (const int*)d_in[1];
    const int*   batch  = (const int*)d_in[2];
    const float* xc     = (const float*)d_in[3];
    const int*   eic    = (const int*)d_in[4];
    const int*   batchc = (const int*)d_in[5];
    const float* W[18];
    for (int i = 0; i < 18; ++i) W[i] = (const float*)d_in[6 + i];
    float* out = (float*)d_out;

    int Nm = in_sizes[2];          // 200000
    int Em = in_sizes[1] / 2;      // 1000000
    int Nc = in_sizes[5];          // 120000
    int Ec = in_sizes[4] / 2;      // 500000

    float *bufA, *bufB, *agg;
    int* cnt;
    cudaGetSymbolAddress((void**)&bufA, g_bufA);
    cudaGetSymbolAddress((void**)&bufB, g_bufB);
    cudaGetSymbolAddress((void**)&agg,  g_agg);
    cudaGetSymbolAddress((void**)&cnt,  g_cnt);

    // Zero output + counts
    zero_f<<<2048, 256>>>(out, (size_t)GRAPHS * 256);
    zero_i<<<(2 * GRAPHS + 255) / 256, 256>>>(cnt, 2 * GRAPHS);

    // Molecular stack -> out cols [0,128)
    run_stack(x, ei, Em, batch, Nm, W + 0, 78, 156, 312, 128,
              bufA, bufB, agg, out, 0, cnt);

    // Clique stack -> out cols [128,256)
    run_stack(xc, eic, Ec, batchc, Nc, W + 9, 92, 184, 368, 128,
              bufA, bufB, agg, out, 128, cnt + GRAPHS);

    // Mean
    pool_div<<<(GRAPHS * 256 + 255) / 256, 256>>>(out, cnt);
}